// round 2
// baseline (speedup 1.0000x reference)
#include <cuda_runtime.h>
#include <cuda_bf16.h>

#define T_STEPS 512
#define BATCH   32
#define DIM     1024
#define NS      64
#define M_TOT   (T_STEPS * BATCH)   // 16384

// Scratch for fused projections: layout [t][b][proj][64], proj = {k,q,v,ax}
__device__ __align__(16) float g_proj[(size_t)M_TOT * 256];  // 16 MB

// ---------------------------------------------------------------------------
// Projection GEMM: C[m][n] = sum_d X[m][d] * W[n][d]
// blockIdx.x: m-tile (128 rows), blockIdx.y: which W (0=k,1=q,2=v,3=ax)
// BM=128, BN=64, BK=32, 128 threads, 8x8 micro-tile per thread.
// ---------------------------------------------------------------------------
__global__ __launch_bounds__(128) void proj_gemm(
    const float* __restrict__ X,
    const float* __restrict__ Wk, const float* __restrict__ Wq,
    const float* __restrict__ Wv, const float* __restrict__ Wa)
{
    __shared__ float Xs[32][128];
    __shared__ float Ws[32][64];

    const float* W = (blockIdx.y == 0) ? Wk :
                     (blockIdx.y == 1) ? Wq :
                     (blockIdx.y == 2) ? Wv : Wa;

    const int tid = threadIdx.x;
    const int m0  = blockIdx.x * 128;
    const int ty  = tid >> 3;   // 0..15 -> m group of 8
    const int tx  = tid & 7;    // 0..7  -> n group of 8

    float acc[8][8];
    #pragma unroll
    for (int i = 0; i < 8; i++)
        #pragma unroll
        for (int j = 0; j < 8; j++) acc[i][j] = 0.f;

    for (int k0 = 0; k0 < DIM; k0 += 32) {
        __syncthreads();
        // Load X tile 128x32 (each thread: its row m=tid, 8 float4 across k)
        #pragma unroll
        for (int i = 0; i < 8; i++) {
            float4 v = *(const float4*)(X + (size_t)(m0 + tid) * DIM + k0 + i * 4);
            Xs[i * 4 + 0][tid] = v.x;
            Xs[i * 4 + 1][tid] = v.y;
            Xs[i * 4 + 2][tid] = v.z;
            Xs[i * 4 + 3][tid] = v.w;
        }
        // Load W tile 64x32
        #pragma unroll
        for (int i = 0; i < 4; i++) {
            int n  = tid & 63;
            int kq = i * 2 + (tid >> 6);
            float4 v = *(const float4*)(W + (size_t)n * DIM + k0 + kq * 4);
            Ws[kq * 4 + 0][n] = v.x;
            Ws[kq * 4 + 1][n] = v.y;
            Ws[kq * 4 + 2][n] = v.z;
            Ws[kq * 4 + 3][n] = v.w;
        }
        __syncthreads();

        #pragma unroll
        for (int kk = 0; kk < 32; kk++) {
            float a[8], w[8];
            #pragma unroll
            for (int i = 0; i < 8; i++) a[i] = Xs[kk][ty * 8 + i];
            #pragma unroll
            for (int j = 0; j < 8; j++) w[j] = Ws[kk][tx * 8 + j];
            #pragma unroll
            for (int i = 0; i < 8; i++)
                #pragma unroll
                for (int j = 0; j < 8; j++)
                    acc[i][j] = fmaf(a[i], w[j], acc[i][j]);
        }
    }

    // Store: C row m = m0+ty*8+i, col = blockIdx.y*64 + tx*8 + j
    #pragma unroll
    for (int i = 0; i < 8; i++) {
        float* dst = g_proj + (size_t)(m0 + ty * 8 + i) * 256 + blockIdx.y * 64 + tx * 8;
        float4 v0 = make_float4(acc[i][0], acc[i][1], acc[i][2], acc[i][3]);
        float4 v1 = make_float4(acc[i][4], acc[i][5], acc[i][6], acc[i][7]);
        *(float4*)(dst + 0) = v0;
        *(float4*)(dst + 4) = v1;
    }
}

// ---------------------------------------------------------------------------
// Recurrent scan. Rows of S are independent:
//   retrieved[i] = S[i]·k ; alpha[i] = sigmoid(ax[i] + d[i]*retrieved[i] + b[i])
//   S[i] = alpha[i]*S[i] + (1-alpha[i])*v[i]*k ; h[i] = S[i]·q
// Grid: 128 CTAs (b = bx>>2, row-group = bx&3 covers 16 rows), 128 threads.
// Thread (row, g) owns S[row][g*8 .. g*8+7] in registers.
// retrieved_{t+1} is fused into the step-t update loop; 2-deep prefetch.
// ---------------------------------------------------------------------------
struct Buf { float k[8]; float q[8]; float v; float ax; };

__global__ __launch_bounds__(128) void scan_kernel(
    const float* __restrict__ S_in,
    const float* __restrict__ d_alpha,
    const float* __restrict__ b_alpha,
    float* __restrict__ out)
{
    const int b   = blockIdx.x >> 2;
    const int rg  = blockIdx.x & 3;
    const int tid = threadIdx.x;
    const int rl  = tid >> 3;        // 0..15
    const int g   = tid & 7;         // 0..7
    const int row = rg * 16 + rl;
    const int c0  = g * 8;

    float S[8];
    {
        const float* sp = S_in + ((size_t)b * NS + row) * NS + c0;
        #pragma unroll
        for (int j = 0; j < 8; j++) S[j] = sp[j];
    }
    const float da = d_alpha[row];
    const float ba = b_alpha[row];

    auto load = [&](int t, Buf& bf) {
        const float* p = g_proj + ((size_t)t * BATCH + b) * 256;
        float4 k0 = *(const float4*)(p + c0);
        float4 k1 = *(const float4*)(p + c0 + 4);
        float4 q0 = *(const float4*)(p + 64 + c0);
        float4 q1 = *(const float4*)(p + 64 + c0 + 4);
        bf.k[0]=k0.x; bf.k[1]=k0.y; bf.k[2]=k0.z; bf.k[3]=k0.w;
        bf.k[4]=k1.x; bf.k[5]=k1.y; bf.k[6]=k1.z; bf.k[7]=k1.w;
        bf.q[0]=q0.x; bf.q[1]=q0.y; bf.q[2]=q0.z; bf.q[3]=q0.w;
        bf.q[4]=q1.x; bf.q[5]=q1.y; bf.q[6]=q1.z; bf.q[7]=q1.w;
        bf.v  = p[128 + row];
        bf.ax = p[192 + row];
    };

    auto red8 = [](float x) {
        x += __shfl_xor_sync(0xffffffffu, x, 1);
        x += __shfl_xor_sync(0xffffffffu, x, 2);
        x += __shfl_xor_sync(0xffffffffu, x, 4);
        return x;
    };

    float r;  // retrieved for the upcoming step

    auto step = [&](int t, Buf& cur, Buf& nxt, Buf& ld) {
        // prefetch t+2 (clamped)
        int tp = (t + 2 < T_STEPS) ? (t + 2) : (T_STEPS - 1);
        load(tp, ld);

        float alpha = 1.f / (1.f + __expf(-(fmaf(da, r, cur.ax) + ba)));
        float c = (1.f - alpha) * cur.v;

        float h0 = 0.f, h1 = 0.f, rn0 = 0.f, rn1 = 0.f;
        #pragma unroll
        for (int j = 0; j < 8; j++) {
            float s = fmaf(alpha, S[j], c * cur.k[j]);
            S[j] = s;
            if (j & 1) { h1 = fmaf(s, cur.q[j], h1); rn1 = fmaf(s, nxt.k[j], rn1); }
            else       { h0 = fmaf(s, cur.q[j], h0); rn0 = fmaf(s, nxt.k[j], rn0); }
        }
        float h = red8(h0 + h1);
        r = red8(rn0 + rn1);

        if (g == 0) {
            float sg = 1.f / (1.f + __expf(-h));
            out[((size_t)t * BATCH + b) * NS + row] = h * h * sg;  // h * silu(h)
        }
    };

    Buf B0, B1, B2;
    load(0, B0);
    load(1, B1);
    {   // retrieved_0 = S_in · k_0
        float t0 = 0.f;
        #pragma unroll
        for (int j = 0; j < 8; j++) t0 = fmaf(S[j], B0.k[j], t0);
        r = red8(t0);
    }

    for (int t = 0; t < 510; t += 3) {
        step(t,     B0, B1, B2);
        step(t + 1, B1, B2, B0);
        step(t + 2, B2, B0, B1);
    }
    step(510, B0, B1, B2);
    step(511, B1, B2, B0);

    // S_final after the output block
    float* sf = out + (size_t)T_STEPS * BATCH * NS + ((size_t)b * NS + row) * NS + c0;
    #pragma unroll
    for (int j = 0; j < 8; j++) sf[j] = S[j];
}

// ---------------------------------------------------------------------------
extern "C" void kernel_launch(void* const* d_in, const int* in_sizes, int n_in,
                              void* d_out, int out_size) {
    const float* x  = (const float*)d_in[0];
    const float* S  = (const float*)d_in[1];
    const float* Wk = (const float*)d_in[2];
    const float* Wv = (const float*)d_in[3];
    const float* Wq = (const float*)d_in[4];
    const float* Wa = (const float*)d_in[5];
    const float* da = (const float*)d_in[6];
    const float* ba = (const float*)d_in[7];
    float* out = (float*)d_out;

    dim3 grid_gemm(M_TOT / 128, 4);
    proj_gemm<<<grid_gemm, 128>>>(x, Wk, Wq, Wv, Wa);
    scan_kernel<<<BATCH * 4, 128>>>(S, da, ba, out);
}